// round 16
// baseline (speedup 1.0000x reference)
#include <cuda_runtime.h>
#include <cuda_bf16.h>
#include <math.h>

// ---------------------------------------------------------------------------
// B=4, T=2048, P=16, J=256, H=4, D=16, MEM=64, K_OUT=192
// N = 64 sequences; tokens M_TOK = 131072
// gemmA (tf32, cp.async, BN=192 single pass): q->LN->g_q, k->LN+L2->g_k,
// v->g_v, beta/alpha fused. Scan: group-direct (phaseG 256-step walks,
// phase2b prefetched compose, phase3g replay). gemmD (tf32) + scatter.
// ---------------------------------------------------------------------------

#define M_TOK   131072
#define JDIM    256
#define NPRE    192
#define NSEQ    64
#define TLEN    2048
#define HEADS   4
#define KOUT    192
#define NGRP    8
#define GTOK    (TLEN / NGRP)   // 256 tokens per group

typedef unsigned long long u64;

// -------- scratch (device globals; no allocation allowed) --------
__device__ float g_Bpack [(size_t)JDIM * NPRE];
__device__ float g_Bpack2[(size_t)64 * KOUT];
__device__ float g_Bpack3[(size_t)JDIM * 8];
__device__ float g_q     [(size_t)M_TOK * 64];
__device__ float g_k     [(size_t)M_TOK * 64];
__device__ float g_v     [(size_t)M_TOK * 64];
__device__ float g_beta  [(size_t)M_TOK * HEADS];
__device__ float g_alpha [(size_t)M_TOK * HEADS];
__device__ float g_o     [(size_t)M_TOK * 64];
__device__ float g_GT[(size_t)NSEQ * NGRP * HEADS * 256];
__device__ float g_GU[(size_t)NSEQ * NGRP * HEADS * 256];
__device__ float g_G [(size_t)NSEQ * NGRP * HEADS * 256];

// ---- helpers ----
__device__ __forceinline__ float tf32r(float x)
{
    unsigned u;
    asm("cvt.rna.tf32.f32 %0, %1;" : "=r"(u) : "f"(x));
    return __uint_as_float(u);
}
__device__ __forceinline__ unsigned fu(float x) { return __float_as_uint(x); }
__device__ __forceinline__ unsigned futf(float x)
{
    unsigned u;
    asm("cvt.rna.tf32.f32 %0, %1;" : "=r"(u) : "f"(x));
    return u;
}

__device__ __forceinline__ u64 pk2(float lo, float hi)
{
    u64 r;
    asm("mov.b64 %0, {%1, %2};" : "=l"(r) : "f"(lo), "f"(hi));
    return r;
}
__device__ __forceinline__ void upk2(u64 v, float& lo, float& hi)
{
    asm("mov.b64 {%0, %1}, %2;" : "=f"(lo), "=f"(hi) : "l"(v));
}
__device__ __forceinline__ u64 ffma2(u64 a, u64 b, u64 c)
{
    u64 d;
    asm("fma.rn.f32x2 %0, %1, %2, %3;" : "=l"(d) : "l"(a), "l"(b), "l"(c));
    return d;
}
__device__ __forceinline__ float pdot8(const u64* r, const u64* k)
{
    u64 a0 = 0ull, a1 = 0ull;
#pragma unroll
    for (int p = 0; p < 4; p++) {
        a0 = ffma2(r[p],     k[p],     a0);
        a1 = ffma2(r[p + 4], k[p + 4], a1);
    }
    float x0, x1, y0, y1;
    upk2(a0, x0, x1); upk2(a1, y0, y1);
    return (x0 + x1) + (y0 + y1);
}

__device__ __forceinline__ unsigned su32(const void* p)
{
    return (unsigned)__cvta_generic_to_shared(p);
}
#define CP16(dst, src) \
    asm volatile("cp.async.cg.shared.global [%0], [%1], 16;" :: "r"(dst), "l"(src))
#define CP_COMMIT() asm volatile("cp.async.commit_group;")
#define CP_WAIT1()  asm volatile("cp.async.wait_group 1;")
#define CP_WAIT0()  asm volatile("cp.async.wait_group 0;")

#define MMA_TF32(c, a, b)                                                     \
    asm volatile("mma.sync.aligned.m16n8k8.row.col.f32.tf32.tf32.f32 "        \
                 "{%0,%1,%2,%3}, {%4,%5,%6,%7}, {%8,%9}, {%0,%1,%2,%3};"      \
                 : "+f"((c)[0]), "+f"((c)[1]), "+f"((c)[2]), "+f"((c)[3])     \
                 : "r"((a)[0]), "r"((a)[1]), "r"((a)[2]), "r"((a)[3]),        \
                   "r"((b)[0]), "r"((b)[1]))

__device__ __forceinline__ float qred(float x)
{
    x += __shfl_xor_sync(0xffffffffu, x, 1);
    x += __shfl_xor_sync(0xffffffffu, x, 2);
    return x;
}
__device__ __forceinline__ float sigm(float x) { return 1.f / (1.f + expf(-x)); }

// ---------------------------------------------------------------------------
// Kernel 0: pack weights (k-major) + round to tf32
// ---------------------------------------------------------------------------
__global__ void pack_kernel(const float* __restrict__ Wq,
                            const float* __restrict__ Wk,
                            const float* __restrict__ Wv,
                            const float* __restrict__ out_w,
                            const float* __restrict__ Wbw,
                            const float* __restrict__ Waw)
{
    int idx = blockIdx.x * blockDim.x + threadIdx.x;
    if (idx < JDIM * NPRE) {
        int k = idx / NPRE;
        int o = idx - k * NPRE;
        float val;
        if      (o < 64)  val = Wq[(size_t)o       * JDIM + k];
        else if (o < 128) val = Wk[(size_t)(o-64)  * JDIM + k];
        else              val = Wv[(size_t)(o-128) * JDIM + k];
        g_Bpack[idx] = tf32r(val);
    }
    int idx2 = idx - JDIM * NPRE;
    if (idx2 >= 0 && idx2 < 64 * KOUT) {
        int k = idx2 / KOUT;
        int o = idx2 - k * KOUT;
        g_Bpack2[idx2] = tf32r(out_w[(size_t)o * 64 + k]);
    }
    int idx3 = idx2 - 64 * KOUT;
    if (idx3 >= 0 && idx3 < JDIM * 8) {
        int k = idx3 >> 3;
        int o = idx3 & 7;
        float val = (o < 4) ? Wbw[(size_t)o * JDIM + k]
                            : Waw[(size_t)(o - 4) * JDIM + k];
        g_Bpack3[idx3] = tf32r(val);
    }
}

// ---------------------------------------------------------------------------
// Kernel A: tf32 GEMM, BM=128 BN=192 BK=16, cp.async 2-stage, 256 threads
// (8 warps: 2M x 4N, warp tile 64x48 = 3 heads). Single pass over x.
// Per-head epilogue by column section: q -> LN, k -> LN+L2, v -> store,
// beta/alpha via extra n=8 MMA on wn==0 warps.
// ---------------------------------------------------------------------------
#define A_KS  20
#define B_KS  196

__global__ __launch_bounds__(256) void gemmA_kernel(
    const float* __restrict__ A,
    const float* __restrict__ lqw, const float* __restrict__ lqb,
    const float* __restrict__ lkw, const float* __restrict__ lkb,
    const float* __restrict__ curv, const float* __restrict__ ent,
    const float* __restrict__ Wbb,  const float* __restrict__ Wab,
    const float* __restrict__ cw,   const float* __restrict__ ew)
{
    __shared__ __align__(16) float As[2][128][A_KS];
    __shared__ __align__(16) float Bs[2][16][B_KS];
    __shared__ __align__(16) float Bs3[2][16][8];

    const int tid  = threadIdx.x;
    const int lane = tid & 31;
    const int wid  = tid >> 5;
    const int g    = lane >> 2;
    const int t    = lane & 3;
    const int wm   = (wid >> 2) * 64;
    const int wn   = (wid & 3) * 48;
    const int m0   = blockIdx.x * 128;
    const bool do_ba = (wn == 0);

    float acc[4][6][4];
#pragma unroll
    for (int i = 0; i < 4; i++)
#pragma unroll
        for (int j = 0; j < 6; j++)
#pragma unroll
            for (int r = 0; r < 4; r++) acc[i][j][r] = 0.f;
    float accB[4][4];
#pragma unroll
    for (int i = 0; i < 4; i++)
#pragma unroll
        for (int r = 0; r < 4; r++) accB[i][r] = 0.f;

    auto load_tiles = [&](int k0, int buf) {
        // A tile: 128 x 16 = 512 float4, 2 per thread
#pragma unroll
        for (int i = 0; i < 2; i++) {
            int e   = i * 256 + tid;
            int row = e >> 2;
            int cq  = (e & 3) * 4;
            CP16(su32(&As[buf][row][cq]),
                 A + (size_t)(m0 + row) * JDIM + k0 + cq);
        }
        // B tile: 16 x 192 = 768 float4, 3 per thread (48 float4 per row)
#pragma unroll
        for (int i = 0; i < 3; i++) {
            int e  = i * 256 + tid;
            int kk = e / 48;
            int cq = (e - kk * 48) * 4;
            CP16(su32(&Bs[buf][kk][cq]),
                 g_Bpack + (size_t)(k0 + kk) * NPRE + cq);
        }
        // beta/alpha weights: 16 x 8 = 32 float4
        if (tid < 32) {
            int kk = tid >> 1;
            int cq = (tid & 1) * 4;
            CP16(su32(&Bs3[buf][kk][cq]),
                 g_Bpack3 + (size_t)(k0 + kk) * 8 + cq);
        }
    };

    load_tiles(0, 0);
    CP_COMMIT();

    for (int kt = 0; kt < 16; kt++) {
        const int cur = kt & 1;
        if (kt < 15) {
            load_tiles((kt + 1) * 16, cur ^ 1);
            CP_COMMIT();
            CP_WAIT1();
        } else {
            CP_WAIT0();
        }
        __syncthreads();

#pragma unroll
        for (int ks = 0; ks < 2; ks++) {
            const int kb = ks * 8;
            unsigned a[4][4], b[6][2];
#pragma unroll
            for (int mt = 0; mt < 4; mt++) {
                int r = wm + mt * 16 + g;
                a[mt][0] = futf(As[cur][r][kb + t]);
                a[mt][1] = futf(As[cur][r + 8][kb + t]);
                a[mt][2] = futf(As[cur][r][kb + t + 4]);
                a[mt][3] = futf(As[cur][r + 8][kb + t + 4]);
            }
#pragma unroll
            for (int nt = 0; nt < 6; nt++) {
                int n = wn + nt * 8 + g;
                b[nt][0] = fu(Bs[cur][kb + t][n]);
                b[nt][1] = fu(Bs[cur][kb + t + 4][n]);
            }
#pragma unroll
            for (int mt = 0; mt < 4; mt++)
#pragma unroll
                for (int nt = 0; nt < 6; nt++)
                    MMA_TF32(acc[mt][nt], a[mt], b[nt]);
            if (do_ba) {
                unsigned b3[2];
                b3[0] = fu(Bs3[cur][kb + t][g]);
                b3[1] = fu(Bs3[cur][kb + t + 4][g]);
#pragma unroll
                for (int mt = 0; mt < 4; mt++)
                    MMA_TF32(accB[mt], a[mt], b3);
            }
        }
        __syncthreads();
    }

    // ---- epilogue: per head (hl = 0..2), section = q/k/v ----
    float wvq0 = lqw[2*t], wvq1 = lqw[2*t+1], wvq2 = lqw[8+2*t], wvq3 = lqw[8+2*t+1];
    float bvq0 = lqb[2*t], bvq1 = lqb[2*t+1], bvq2 = lqb[8+2*t], bvq3 = lqb[8+2*t+1];
    float wvk0 = lkw[2*t], wvk1 = lkw[2*t+1], wvk2 = lkw[8+2*t], wvk3 = lkw[8+2*t+1];
    float bvk0 = lkb[2*t], bvk1 = lkb[2*t+1], bvk2 = lkb[8+2*t], bvk3 = lkb[8+2*t+1];
    const float inv16 = 1.f / 16.f;

#pragma unroll
    for (int mt = 0; mt < 4; mt++) {
#pragma unroll
        for (int hl = 0; hl < 3; hl++) {
            const int cb  = wn + hl * 16;          // global col of head start
            const int sec = cb >> 6;               // 0=q, 1=k, 2=v
            const int nt0 = 2 * hl, nt1 = 2 * hl + 1;
#pragma unroll
            for (int half = 0; half < 2; half++) {
                const int c0 = half * 2, c1 = half * 2 + 1;
                float x0 = acc[mt][nt0][c0], x1 = acc[mt][nt0][c1];
                float x2 = acc[mt][nt1][c0], x3 = acc[mt][nt1][c1];
                int row = m0 + wm + mt * 16 + g + half * 8;
                int cl  = (cb & 63) + 2 * t;       // col within section
                if (sec == 2) {
                    *(float2*)(g_v + (size_t)row * 64 + cl)     = make_float2(x0, x1);
                    *(float2*)(g_v + (size_t)row * 64 + cl + 8) = make_float2(x2, x3);
                    continue;
                }
                float mu = qred(x0 + x1 + x2 + x3) * inv16;
                float d0 = x0 - mu, d1 = x1 - mu, d2 = x2 - mu, d3 = x3 - mu;
                float var = qred(d0*d0 + d1*d1 + d2*d2 + d3*d3) * inv16;
                float rs = 1.f / sqrtf(var + 1e-5f);
                if (sec == 0) {
                    float n0v = d0 * rs * wvq0 + bvq0;
                    float n1v = d1 * rs * wvq1 + bvq1;
                    float n2v = d2 * rs * wvq2 + bvq2;
                    float n3v = d3 * rs * wvq3 + bvq3;
                    *(float2*)(g_q + (size_t)row * 64 + cl)     = make_float2(n0v, n1v);
                    *(float2*)(g_q + (size_t)row * 64 + cl + 8) = make_float2(n2v, n3v);
                } else {
                    float n0v = d0 * rs * wvk0 + bvk0;
                    float n1v = d1 * rs * wvk1 + bvk1;
                    float n2v = d2 * rs * wvk2 + bvk2;
                    float n3v = d3 * rs * wvk3 + bvk3;
                    float ss = qred(n0v*n0v + n1v*n1v + n2v*n2v + n3v*n3v);
                    float sc = 1.f / fmaxf(sqrtf(ss), 1e-12f);
                    n0v *= sc; n1v *= sc; n2v *= sc; n3v *= sc;
                    *(float2*)(g_k + (size_t)row * 64 + cl)     = make_float2(n0v, n1v);
                    *(float2*)(g_k + (size_t)row * 64 + cl + 8) = make_float2(n2v, n3v);
                }
            }
        }
    }

    // beta/alpha epilogue (wn==0 warps)
    if (do_ba) {
        const int bidx = m0 >> 15;
        const float Kv = fminf(fabsf(curv[bidx]), 10.f);
        const float Sv = fminf(fmaxf(ent[bidx], 0.f), 5.f);
        const int c0 = 2 * t, c1 = 2 * t + 1;
        const bool isA = (t >= 2);
        const int h0 = isA ? c0 - 4 : c0;
        const int h1 = isA ? c1 - 4 : c1;
        const float off0 = isA ? Wab[h0] : Wbb[h0];
        const float off1 = isA ? Wab[h1] : Wbb[h1];
        const float mod0 = isA ? Sv * ew[h0] : Kv * cw[h0];
        const float mod1 = isA ? Sv * ew[h1] : Kv * cw[h1];
        float* dstba = isA ? g_alpha : g_beta;
#pragma unroll
        for (int mt = 0; mt < 4; mt++) {
#pragma unroll
            for (int half = 0; half < 2; half++) {
                int row = m0 + wm + mt * 16 + g + half * 8;
                float p0 = accB[mt][half * 2 + 0];
                float p1 = accB[mt][half * 2 + 1];
                dstba[(size_t)row * HEADS + h0] = sigm(sigm(p0 + off0) + mod0);
                dstba[(size_t)row * HEADS + h1] = sigm(sigm(p1 + off1) + mod1);
            }
        }
    }
}

// ---------------------------------------------------------------------------
// Scan phaseG: group operators (T_g, U_g) via 256-step walk.
// Grid (NSEQ, NGRP), 32 threads; thread (h, i2) owns rows i2 and i2+8.
// ---------------------------------------------------------------------------
__global__ __launch_bounds__(32) void scan_phaseG()
{
    const int n   = blockIdx.x;
    const int grp = blockIdx.y;
    const int tid = threadIdx.x;
    const int h   = tid >> 3;
    const int i2  = tid & 7;
    const int r0  = i2;
    const int r1  = i2 + 8;

    __shared__ __align__(16) float ks[2][32 * 64];
    __shared__ __align__(16) float vs[2][32 * 64];
    __shared__ __align__(16) float bs[2][128];
    __shared__ __align__(16) float as_[2][128];

    auto load_slab = [&](int s, int buf) {
        const size_t tok = (size_t)n * TLEN + (size_t)grp * GTOK + s * 32;
        const float4* gk = (const float4*)(g_k + tok * 64);
        const float4* gv = (const float4*)(g_v + tok * 64);
#pragma unroll
        for (int e = 0; e < 16; e++) {
            CP16(su32(&((float4*)ks[buf])[tid + e * 32]), gk + tid + e * 32);
            CP16(su32(&((float4*)vs[buf])[tid + e * 32]), gv + tid + e * 32);
        }
        CP16(su32(&((float4*)bs[buf])[tid]),  (const float4*)(g_beta  + tok * 4) + tid);
        CP16(su32(&((float4*)as_[buf])[tid]), (const float4*)(g_alpha + tok * 4) + tid);
    };

    u64 Ta[8], Tb[8], Ua[8], Ub[8];
#pragma unroll
    for (int p = 0; p < 8; p++) {
        Ta[p] = pk2((2*p == r0) ? 1.f : 0.f, (2*p+1 == r0) ? 1.f : 0.f);
        Tb[p] = pk2((2*p == r1) ? 1.f : 0.f, (2*p+1 == r1) ? 1.f : 0.f);
        Ua[p] = 0ull; Ub[p] = 0ull;
    }

    load_slab(0, 0);
    CP_COMMIT();

    for (int s = 0; s < 8; s++) {
        const int cur = s & 1;
        if (s < 7) {
            load_slab(s + 1, cur ^ 1);
            CP_COMMIT();
            CP_WAIT1();
        } else {
            CP_WAIT0();
        }
        __syncwarp();

        for (int tt = 0; tt < 32; tt++) {
            const u64* kp2 = (const u64*)(ks[cur] + tt * 64 + h * 16);
            u64 k2[8];
#pragma unroll
            for (int p = 0; p < 8; p++) k2[p] = kp2[p];

            float Tka = pdot8(Ta, k2);
            float Tkb = pdot8(Tb, k2);
            float Uka = pdot8(Ua, k2);
            float Ukb = pdot8(Ub, k2);

            float a  = as_[cur][tt * HEADS + h];
            float b  = bs [cur][tt * HEADS + h];
            float va = vs [cur][tt * 64 + h * 16 + r0];
            float vb = vs [cur][tt * 64 + h * 16 + r1];
            float cTa = -a * Tka, cTb = -a * Tkb;
            float cUa = b * va - a * Uka;
            float cUb = b * vb - a * Ukb;
            u64 cTa2 = pk2(cTa, cTa), cTb2 = pk2(cTb, cTb);
            u64 cUa2 = pk2(cUa, cUa), cUb2 = pk2(cUb, cUb);

#pragma unroll
            for (int p = 0; p < 8; p++) {
                Ta[p] = ffma2(k2[p], cTa2, Ta[p]);
                Tb[p] = ffma2(k2[p], cTb2, Tb[p]);
                Ua[p] = ffma2(k2[p], cUa2, Ua[p]);
                Ub[p] = ffma2(k2[p], cUb2, Ub[p]);
            }
        }
        __syncwarp();
    }

    const size_t og = ((size_t)(n * NGRP + grp) * HEADS + h) * 256;
    u64* Td0 = (u64*)(g_GT + og + r0 * 16);
    u64* Td1 = (u64*)(g_GT + og + r1 * 16);
    u64* Ud0 = (u64*)(g_GU + og + r0 * 16);
    u64* Ud1 = (u64*)(g_GU + og + r1 * 16);
#pragma unroll
    for (int p = 0; p < 8; p++) {
        Td0[p] = Ta[p]; Td1[p] = Tb[p];
        Ud0[p] = Ua[p]; Ud1[p] = Ub[p];
    }
}

// ---------------------------------------------------------------------------
// Scan phase2b: serial over 8 group operators per n with register prefetch.
// ---------------------------------------------------------------------------
__global__ __launch_bounds__(64) void scan_phase2b()
{
    const int n   = blockIdx.x;
    const int tid = threadIdx.x;
    const int h   = tid >> 4;
    const int i   = tid & 15;

    __shared__ __align__(16) float Ts[2][HEADS * 256];
    __shared__ __align__(16) float Us[2][HEADS * 256];

    float Gr[16];
#pragma unroll
    for (int j = 0; j < 16; j++) Gr[j] = 0.f;

    {
        const size_t og = (size_t)(n * NGRP) * HEADS * 256;
        const float4* Tg = (const float4*)(g_GT + og);
        const float4* Ug = (const float4*)(g_GU + og);
#pragma unroll
        for (int e = 0; e < 4; e++) {
            ((float4*)Ts[0])[tid + e * 64] = Tg[tid + e * 64];
            ((float4*)Us[0])[tid + e * 64] = Ug[tid + e * 64];
        }
    }
    __syncthreads();

    for (int grp = 0; grp < NGRP; grp++) {
        const int cur = grp & 1;
        float4 pfT[4], pfU[4];
        if (grp + 1 < NGRP) {
            const size_t ogn = (size_t)(n * NGRP + grp + 1) * HEADS * 256;
            const float4* Tg = (const float4*)(g_GT + ogn);
            const float4* Ug = (const float4*)(g_GU + ogn);
#pragma unroll
            for (int e = 0; e < 4; e++) {
                pfT[e] = Tg[tid + e * 64];
                pfU[e] = Ug[tid + e * 64];
            }
        }

        // store group start state
        {
            const size_t og = (size_t)(n * NGRP + grp) * HEADS * 256;
            float* Gd = g_G + og + (size_t)h * 256 + i * 16;
#pragma unroll
            for (int e = 0; e < 4; e++)
                *(float4*)(Gd + 4*e) = make_float4(Gr[4*e], Gr[4*e+1], Gr[4*e+2], Gr[4*e+3]);
        }

        u64 Gn2[8];
        const u64* Uh = (const u64*)(Us[cur] + h * 256 + i * 16);
#pragma unroll
        for (int p = 0; p < 8; p++) Gn2[p] = Uh[p];
        const float* Th = Ts[cur] + h * 256;
#pragma unroll
        for (int u = 0; u < 16; u++) {
            u64 gu2 = pk2(Gr[u], Gr[u]);
            const u64* Tu = (const u64*)(Th + u * 16);
#pragma unroll
            for (int p = 0; p < 8; p++) Gn2[p] = ffma2(gu2, Tu[p], Gn2[p]);
        }
#pragma unroll
        for (int p = 0; p < 8; p++) upk2(Gn2[p], Gr[2*p], Gr[2*p+1]);

        if (grp + 1 < NGRP) {
#pragma unroll
            for (int e = 0; e < 4; e++) {
                ((float4*)Ts[cur ^ 1])[tid + e * 64] = pfT[e];
                ((float4*)Us[cur ^ 1])[tid + e * 64] = pfU[e];
            }
        }
        __syncthreads();
    }
}

// ---------------------------------------------------------------------------
// Scan phase3g: replay each group of 256 tokens from g_G, emit outputs.
// Grid (NSEQ, NGRP), 32 threads; 16-token cp.async double-buffered slabs.
// ---------------------------------------------------------------------------
__global__ __launch_bounds__(32) void scan_phase3g()
{
    const int n   = blockIdx.x;
    const int grp = blockIdx.y;
    const int tid = threadIdx.x;
    const int h   = tid >> 3;
    const int i2  = tid & 7;
    const int r0  = i2;
    const int r1  = i2 + 8;

    __shared__ __align__(16) float ks[2][16 * 64];
    __shared__ __align__(16) float qs[2][16 * 64];
    __shared__ __align__(16) float vs[2][16 * 64];
    __shared__ __align__(16) float bs[2][64];
    __shared__ __align__(16) float as_[2][64];

    auto load_slab = [&](int s, int buf) {
        const size_t tok = (size_t)n * TLEN + (size_t)grp * GTOK + s * 16;
        const float4* gk = (const float4*)(g_k + tok * 64);
        const float4* gq = (const float4*)(g_q + tok * 64);
        const float4* gv = (const float4*)(g_v + tok * 64);
#pragma unroll
        for (int e = 0; e < 8; e++) {
            CP16(su32(&((float4*)ks[buf])[tid + e * 32]), gk + tid + e * 32);
            CP16(su32(&((float4*)qs[buf])[tid + e * 32]), gq + tid + e * 32);
            CP16(su32(&((float4*)vs[buf])[tid + e * 32]), gv + tid + e * 32);
        }
        if (tid < 16) {
            CP16(su32(&((float4*)bs[buf])[tid]),  (const float4*)(g_beta  + tok * 4) + tid);
            CP16(su32(&((float4*)as_[buf])[tid]), (const float4*)(g_alpha + tok * 4) + tid);
        }
    };

    u64 Ma[8], Mb[8];
    {
        const size_t og = ((size_t)(n * NGRP + grp) * HEADS + h) * 256;
        const u64* S0 = (const u64*)(g_G + og + r0 * 16);
        const u64* S1 = (const u64*)(g_G + og + r1 * 16);
#pragma unroll
        for (int p = 0; p < 8; p++) { Ma[p] = S0[p]; Mb[p] = S1[p]; }
    }

    load_slab(0, 0);
    CP_COMMIT();

    for (int s = 0; s < 16; s++) {
        const int cur = s & 1;
        if (s < 15) {
            load_slab(s + 1, cur ^ 1);
            CP_COMMIT();
            CP_WAIT1();
        } else {
            CP_WAIT0();
        }
        __syncwarp();

        const size_t tokbase = ((size_t)n * TLEN + (size_t)grp * GTOK + s * 16) * 64;
        for (int tt = 0; tt < 16; tt++) {
            const u64* kp2 = (const u64*)(ks[cur] + tt * 64 + h * 16);
            u64 k2[8];
#pragma unroll
            for (int p = 0; p < 8; p++) k2[p] = kp2[p];

            float Mka = pdot8(Ma, k2);
            float Mkb = pdot8(Mb, k2);

            float a  = as_[cur][tt * HEADS + h];
            float b  = bs [cur][tt * HEADS + h];
            float va = vs [cur][tt * 64 + h * 16 + r0];
            float vb = vs [cur][tt * 64 + h * 16 + r1];
            float ca = b * va - a * Mka;
            float cb = b * vb - a * Mkb;
            u64 ca2 = pk2(ca, ca), cb2 = pk2(cb, cb);

#pragma unroll
            for (int p = 0; p < 8; p++) {
                Ma[p] = ffma2(k2[p], ca2, Ma[p]);
                Mb[p] = ffma2(k2[p], cb2, Mb[p]);
            }

            const u64* qp2 = (const u64*)(qs[cur] + tt * 64 + h * 16);
            u64 q2[8];
#pragma unroll
            for (int p = 0; p < 8; p++) q2[p] = qp2[p];
            float oa  = pdot8(Ma, q2);
            float ob_ = pdot8(Mb, q2);

            g_o[tokbase + tt * 64 + h * 16 + r0] = oa;
            g_o[tokbase + tt * 64 + h * 16 + r1] = ob_;
        }
        __syncwarp();
    }
}

// ---------------------------------------------------------------------------
// Kernel D (tf32, cp.async 2-stage, BK=16): fib = o @ out_w^T + out_b,
// scatter to (B,T,P,K).
// ---------------------------------------------------------------------------
#define D_BKS 68

__global__ __launch_bounds__(128) void gemmD_kernel(const float* __restrict__ ob,
                                                    float* __restrict__ out)
{
    __shared__ __align__(16) float As[2][128][A_KS];
    __shared__ __align__(16) float Bs[2][16][D_BKS];

    const int tid  = threadIdx.x;
    const int lane = tid & 31;
    const int wid  = tid >> 5;
    const int g    = lane >> 2;
    const int t    = lane & 3;
    const int wm   = (wid >> 1) * 64;
    const int wn   = (wid & 1) * 32;
    const int m0   = blockIdx.y * 128;
    const int n0   = blockIdx.x * 64;

    float acc[4][4][4];
#pragma unroll
    for (int i = 0; i < 4; i++)
#pragma unroll
        for (int j = 0; j < 4; j++)
#pragma unroll
            for (int r = 0; r < 4; r++) acc[i][j][r] = 0.f;

    auto load_tiles = [&](int k0, int buf) {
#pragma unroll
        for (int i = 0; i < 4; i++) {
            int e   = i * 128 + tid;
            int row = e >> 2;
            int cq  = (e & 3) * 4;
            CP16(su32(&As[buf][row][cq]),
                 g_o + (size_t)(m0 + row) * 64 + k0 + cq);
        }
#pragma unroll
        for (int i = 0; i < 2; i++) {
            int e  = i * 128 + tid;
            int kk = e >> 4;
            int cq = (e & 15) * 4;
            CP16(su32(&Bs[buf][kk][cq]),
                 g_Bpack2 + (size_t)(k0 + kk) * KOUT + n0 + cq);
        }
    };

    load_tiles(0, 0);
    CP_COMMIT();

    for (int kt = 0; kt < 4; kt++) {
        const int cur = kt & 1;
        if (kt < 3) {
            load_tiles((kt + 1) * 16, cur ^ 1);
            CP_COMMIT();
            CP_WAIT1();
        } else {
            CP_WAIT0();
        }
        __syncthreads();

#pragma unroll
        for (int ks = 0; ks < 2; ks++) {
            const int kb = ks * 8;
            unsigned a[4][4], b[4][2];
#pragma unroll
            for (int mt = 0; mt < 4; mt++) {
                int r = wm + mt * 16 + g;
                a[mt][0] = futf(As[cur][r][kb + t]);
                a[mt][1] = futf(As[cur][r + 8][kb + t]);
                a[mt][2] = futf(As[cur][r][kb + t + 4]);
                a[mt][3] = futf(As[cur][r + 8][kb + t + 4]);
            }
#pragma unroll
            for (int nt = 0; nt < 4; nt++) {
                int n = wn + nt * 8 + g;
                b[nt][0] = fu(Bs[cur][kb + t][n]);
                b[nt][1] = fu(Bs[cur][kb + t + 4][n]);
            }
#pragma unroll
            for (int mt = 0; mt < 4; mt++)
#pragma unroll
                for (int nt = 0; nt < 4; nt++)
                    MMA_TF32(acc[mt][nt], a[mt], b[nt]);
        }
        __syncthreads();
    }

    const int nseq = m0 >> 11;
    const int tb   = m0 & 2047;
    const int bb   = nseq >> 4;
    const int pp   = nseq & 15;
#pragma unroll
    for (int mt = 0; mt < 4; mt++) {
#pragma unroll
        for (int nt = 0; nt < 4; nt++) {
            int r   = wm + mt * 16 + g;
            int col = n0 + wn + nt * 8 + 2 * t;
            float b0 = ob[col], b1 = ob[col + 1];
            int t1 = tb + r;
            size_t d1 = (((size_t)bb * TLEN + t1) * 16 + pp) * KOUT + col;
            *(float2*)(out + d1) = make_float2(acc[mt][nt][0] + b0,
                                               acc[mt][nt][1] + b1);
            int t2 = t1 + 8;
            size_t d2 = (((size_t)bb * TLEN + t2) * 16 + pp) * KOUT + col;
            *(float2*)(out + d2) = make_float2(acc[mt][nt][2] + b0,
                                               acc[mt][nt][3] + b1);
        }
    }
}

// ---------------------------------------------------------------------------
// launch
// ---------------------------------------------------------------------------
extern "C" void kernel_launch(void* const* d_in, const int* in_sizes, int n_in,
                              void* d_out, int out_size)
{
    const float* joint = (const float*)d_in[0];
    const float* curv  = (const float*)d_in[1];
    const float* ent   = (const float*)d_in[2];
    const float* Wq    = (const float*)d_in[3];
    const float* Wk    = (const float*)d_in[4];
    const float* Wv    = (const float*)d_in[5];
    const float* Wbw   = (const float*)d_in[6];
    const float* Wbb   = (const float*)d_in[7];
    const float* Waw   = (const float*)d_in[8];
    const float* Wab   = (const float*)d_in[9];
    const float* cw    = (const float*)d_in[10];
    const float* ew    = (const float*)d_in[11];
    const float* out_w = (const float*)d_in[12];
    const float* out_b = (const float*)d_in[13];
    const float* lqw   = (const float*)d_in[14];
    const float* lqb   = (const float*)d_in[15];
    const float* lkw   = (const float*)d_in[16];
    const float* lkb   = (const float*)d_in[17];
    float* out = (float*)d_out;

    pack_kernel<<<256, 256>>>(Wq, Wk, Wv, out_w, Wbw, Waw);

    gemmA_kernel<<<M_TOK / 128, 256>>>(joint, lqw, lqb, lkw, lkb,
                                       curv, ent, Wbb, Wab, cw, ew);

    scan_phaseG<<<dim3(NSEQ, NGRP), 32>>>();
    scan_phase2b<<<NSEQ, 64>>>();
    scan_phase3g<<<dim3(NSEQ, NGRP), 32>>>();

    gemmD_kernel<<<dim3(KOUT / 64, M_TOK / 128), 128>>>(out_b, out);
}